// round 10
// baseline (speedup 1.0000x reference)
#include <cuda_runtime.h>
#include <cuda_bf16.h>

// Problem shape (fixed by the dataset)
#define Bv 8
#define Cv 256
#define Lv 4096
#define Kv 8
#define Gv 2              // channels per CTA, packed into f32x2 lanes
#define TPB 256
#define NJ (Lv / 4)       // float4s per row = 1024
#define ITERS (NJ / TPB)  // 4

#define SMEM_BYTES (2 * Gv * Lv * 4)

// ---------------------------------------------------------------------------
// Blackwell packed f32x2 helpers (PTX-only; ptxas never auto-fuses FFMA2).
// Lane .x = channel 0, lane .y = channel 1. Per-lane math identical to scalar.
// ---------------------------------------------------------------------------
typedef unsigned long long ull;

__device__ __forceinline__ ull pk2(float lo, float hi) {
    ull r; asm("mov.b64 %0, {%1, %2};" : "=l"(r) : "f"(lo), "f"(hi)); return r;
}
__device__ __forceinline__ float2 upk2(ull v) {
    float2 f; asm("mov.b64 {%0, %1}, %2;" : "=f"(f.x), "=f"(f.y) : "l"(v)); return f;
}
__device__ __forceinline__ ull bc2(float v) { return pk2(v, v); }
__device__ __forceinline__ ull fma2(ull a, ull b, ull c) {
    ull d; asm("fma.rn.f32x2 %0, %1, %2, %3;" : "=l"(d) : "l"(a), "l"(b), "l"(c)); return d;
}
__device__ __forceinline__ ull mul2(ull a, ull b) {
    ull d; asm("mul.rn.f32x2 %0, %1, %2;" : "=l"(d) : "l"(a), "l"(b)); return d;
}
__device__ __forceinline__ ull add2(ull a, ull b) {
    ull d; asm("add.rn.f32x2 %0, %1, %2;" : "=l"(d) : "l"(a), "l"(b)); return d;
}

// ---------------------------------------------------------------------------
// Math (per lane):
//  softmax identity  w_k(l) = E[l-k] / sum_k' E[l-k'],  E = exp(dt)
//  windowed numerators num_c = sum_{m=c+1}^{c+8} E[m]*x[m] (shared products);
//  at = num * rcp(den);  at[l<7] = 0 exactly (reference BIG sentinel);
//  ap = sum_k kt[k] x[l-k].
// ---------------------------------------------------------------------------
template<bool FIRST>
__device__ __forceinline__ void pass1_iter(
    const int j,
    const float4* __restrict__ dtr,
    const float4* __restrict__ xr0,
    const float4* __restrict__ xr1,
    const ull*    __restrict__ ktp,     // [Kv] kt broadcast-packed
    float4* __restrict__ sat,           // [Gv*NJ]
    float4* __restrict__ sap,           // [Gv*NJ]
    ull*    __restrict__ gp)            // [3] packed Gram accumulators
{
    const float4 zero4 = make_float4(0.f, 0.f, 0.f, 0.f);

    // dt window [4j-8 .. 4j+3] -> E = exp(dt)  (scalar: shared by both lanes)
    float4 dm2 = FIRST ? ((j >= 2) ? dtr[j - 2] : zero4) : dtr[j - 2];
    float4 dm1 = FIRST ? ((j >= 1) ? dtr[j - 1] : zero4) : dtr[j - 1];
    float4 dd0 = dtr[j];
    float Ew[12] = {dm2.x, dm2.y, dm2.z, dm2.w,
                    dm1.x, dm1.y, dm1.z, dm1.w,
                    dd0.x, dd0.y, dd0.z, dd0.w};
#pragma unroll
    for (int m = 0; m < 12; m++) Ew[m] = __expf(Ew[m]);

    // reciprocal 8-tap sums (scalar, shared factored partials)
    float inv[4];
    {
        float c45  = Ew[4] + Ew[5];
        float c67  = Ew[6] + Ew[7];
        float core = (c45 + c67) + Ew[8];          // E[4..8]
        float s23  = Ew[2] + Ew[3];
        float s910 = Ew[9] + Ew[10];
        inv[0] = __fdividef(1.0f, core + (Ew[1] + s23));    // E[1..8]
        inv[1] = __fdividef(1.0f, core + (s23 + Ew[9]));    // E[2..9]
        inv[2] = __fdividef(1.0f, core + (Ew[3] + s910));   // E[3..10]
        inv[3] = __fdividef(1.0f, core + (s910 + Ew[11]));  // E[4..11]
    }

    // x windows, both channels, packed (lane0 = ch0, lane1 = ch1)
    float4 am2 = FIRST ? ((j >= 2) ? xr0[j - 2] : zero4) : xr0[j - 2];
    float4 am1 = FIRST ? ((j >= 1) ? xr0[j - 1] : zero4) : xr0[j - 1];
    float4 a0  = xr0[j];
    float4 bm2 = FIRST ? ((j >= 2) ? xr1[j - 2] : zero4) : xr1[j - 2];
    float4 bm1 = FIRST ? ((j >= 1) ? xr1[j - 1] : zero4) : xr1[j - 1];
    float4 b0  = xr1[j];
    ull xp[12] = {
        pk2(am2.x, bm2.x), pk2(am2.y, bm2.y), pk2(am2.z, bm2.z), pk2(am2.w, bm2.w),
        pk2(am1.x, bm1.x), pk2(am1.y, bm1.y), pk2(am1.z, bm1.z), pk2(am1.w, bm1.w),
        pk2(a0.x,  b0.x),  pk2(a0.y,  b0.y),  pk2(a0.z,  b0.z),  pk2(a0.w,  b0.w)};

    // packed products p[m] = E[m]*x[m] and windowed numerators
    ull num[4];
    {
        ull p1 = mul2(bc2(Ew[1]),  xp[1]),  p2  = mul2(bc2(Ew[2]),  xp[2]);
        ull p3 = mul2(bc2(Ew[3]),  xp[3]),  p4  = mul2(bc2(Ew[4]),  xp[4]);
        ull p5 = mul2(bc2(Ew[5]),  xp[5]),  p6  = mul2(bc2(Ew[6]),  xp[6]);
        ull p7 = mul2(bc2(Ew[7]),  xp[7]),  p8  = mul2(bc2(Ew[8]),  xp[8]);
        ull p9 = mul2(bc2(Ew[9]),  xp[9]),  p10 = mul2(bc2(Ew[10]), xp[10]);
        ull p11 = mul2(bc2(Ew[11]), xp[11]);
        ull c45  = add2(p4, p5);
        ull c67  = add2(p6, p7);
        ull core = add2(add2(c45, c67), p8);       // p[4..8]
        ull s23  = add2(p2, p3);
        ull s910 = add2(p9, p10);
        num[0] = add2(core, add2(p1, s23));        // p[1..8]
        num[1] = add2(core, add2(s23, p9));        // p[2..9]
        num[2] = add2(core, add2(p3, s910));       // p[3..10]
        num[3] = add2(core, add2(s910, p11));      // p[4..11]
    }

    // packed ap convolution + at + Gram
    ull atp[4], app[4];
#pragma unroll
    for (int c = 0; c < 4; c++) {
        ull a = mul2(ktp[0], xp[8 + c]);
#pragma unroll
        for (int k = 1; k < Kv; k++)
            a = fma2(ktp[k], xp[8 + c - k], a);
        app[c] = a;
        ull t = mul2(num[c], bc2(inv[c]));
        if (FIRST) {
            if (4 * j + c < Kv - 1) t = 0ull;      // BIG-sentinel mask (both lanes)
        }
        atp[c] = t;
        gp[0] = fma2(t, t, gp[0]);
        gp[1] = fma2(t, a, gp[1]);
        gp[2] = fma2(a, a, gp[2]);
    }

    // unpack to per-channel float4s and store
    float2 t0 = upk2(atp[0]), t1 = upk2(atp[1]), t2 = upk2(atp[2]), t3 = upk2(atp[3]);
    float2 q0 = upk2(app[0]), q1 = upk2(app[1]), q2 = upk2(app[2]), q3 = upk2(app[3]);
    sat[j]      = make_float4(t0.x, t1.x, t2.x, t3.x);
    sat[NJ + j] = make_float4(t0.y, t1.y, t2.y, t3.y);
    sap[j]      = make_float4(q0.x, q1.x, q2.x, q3.x);
    sap[NJ + j] = make_float4(q0.y, q1.y, q2.y, q3.y);
}

__global__ void __launch_bounds__(TPB, 3) fused_kernel(
    const float* __restrict__ x,
    const float* __restrict__ dt,
    const float* __restrict__ kt,
    float* __restrict__ out)
{
    extern __shared__ float smem[];
    float4* sat = (float4*)smem;               // [Gv][NJ]
    float4* sap = (float4*)(smem + Gv * Lv);   // [Gv][NJ]
    __shared__ float sred[8][Gv * 3];
    __shared__ float scoef[Gv][2];

    const int b   = blockIdx.x >> 7;           // / (Cv/Gv = 128)
    const int c0  = (blockIdx.x & 127) * Gv;
    const int tid = threadIdx.x;
    const int lid = tid & 31;
    const int wid = tid >> 5;

    const float4* dtr = (const float4*)(dt + (size_t)b * Lv);
    const float4* xr0 = (const float4*)(x + (size_t)(b * Cv + c0 + 0) * Lv);
    const float4* xr1 = (const float4*)(x + (size_t)(b * Cv + c0 + 1) * Lv);

    ull ktp[Kv];
#pragma unroll
    for (int k = 0; k < Kv; k++) ktp[k] = bc2(__ldg(&kt[k]));

    ull gp[3] = {0ull, 0ull, 0ull};            // packed Gram accumulators

    // Iteration 0 (peeled: halo zero-fill + l<7 mask live only here)
    pass1_iter<true>(tid, dtr, xr0, xr1, ktp, sat, sap, gp);
    // Iterations 1..3 (guard-free)
#pragma unroll 1
    for (int i = 1; i < ITERS; i++)
        pass1_iter<false>(tid + i * TPB, dtr, xr0, xr1, ktp, sat, sap, gp);

    // ---- unpack Gram, block reduction of 6 scalars ----
    float gr[Gv * 3];
    {
        float2 g0 = upk2(gp[0]), g1 = upk2(gp[1]), g2 = upk2(gp[2]);
        gr[0] = g0.x; gr[1] = g1.x; gr[2] = g2.x;   // channel 0
        gr[3] = g0.y; gr[4] = g1.y; gr[5] = g2.y;   // channel 1
    }
#pragma unroll
    for (int q = 0; q < Gv * 3; q++) {
        float v = gr[q];
#pragma unroll
        for (int o = 16; o > 0; o >>= 1)
            v += __shfl_xor_sync(0xffffffffu, v, o);
        if (lid == 0) sred[wid][q] = v;
    }
    __syncthreads();
    if (tid < Gv) {
        float G00 = 0.f, G01 = 0.f, G11 = 0.f;
#pragma unroll
        for (int wq = 0; wq < 8; wq++) {
            G00 += sred[wq][tid * 3 + 0];
            G01 += sred[wq][tid * 3 + 1];
            G11 += sred[wq][tid * 3 + 2];
        }
        // scores row0 = softmax([G00,G01]); row1 = softmax([G01,G11])
        // out = 0.5*((s00+s10)*at + ((1-s00)+(1-s10))*ap)
        float s00 = 1.0f / (1.0f + __expf(G01 - G00));
        float s10 = 1.0f / (1.0f + __expf(G11 - G01));
        scoef[tid][0] = 0.5f * (s00 + s10);
        scoef[tid][1] = 0.5f * ((1.0f - s00) + (1.0f - s10));
    }
    __syncthreads();

    // ---- pass 2: out = ca*at + cb*ap (LDS.128 -> STG.128) ----
#pragma unroll
    for (int g = 0; g < Gv; g++) {
        const float ca = scoef[g][0];
        const float cb = scoef[g][1];
        float4* orow = (float4*)(out + (size_t)(b * Cv + c0 + g) * Lv);
#pragma unroll
        for (int i = 0; i < ITERS; i++) {
            const int j = tid + i * TPB;
            float4 a = sat[g * NJ + j];
            float4 p = sap[g * NJ + j];
            float4 o;
            o.x = fmaf(ca, a.x, cb * p.x);
            o.y = fmaf(ca, a.y, cb * p.y);
            o.z = fmaf(ca, a.z, cb * p.z);
            o.w = fmaf(ca, a.w, cb * p.w);
            orow[j] = o;
        }
    }
}

// ---------------------------------------------------------------------------
extern "C" void kernel_launch(void* const* d_in, const int* in_sizes, int n_in,
                              void* d_out, int out_size) {
    const float* x  = (const float*)d_in[0];   // (B, C, L) f32
    const float* dt = (const float*)d_in[1];   // (B, L)    f32
    const float* kt = (const float*)d_in[2];   // (1, 1, K) f32
    float* out = (float*)d_out;                // (B, C, L) f32

    cudaFuncSetAttribute(fused_kernel,
                         cudaFuncAttributeMaxDynamicSharedMemorySize, SMEM_BYTES);

    fused_kernel<<<Bv * Cv / Gv, TPB, SMEM_BYTES>>>(x, dt, kt, out);
}

// round 11
// speedup vs baseline: 1.0965x; 1.0965x over previous
#include <cuda_runtime.h>
#include <cuda_bf16.h>

// Problem shape (fixed by the dataset)
#define Bv 8
#define Cv 256
#define Lv 4096
#define Kv 8
#define Gv 2              // channels per CTA (share weight computation)
#define TPB 256
#define NJ (Lv / 4)       // float4s per row = 1024
#define ITERS (NJ / TPB)  // 4

#define SMEM_BYTES (2 * Gv * Lv * 4)

// ---------------------------------------------------------------------------
// Math:
//  softmax identity  w_k(l) = E[l-k] / sum_k' E[l-k'],  E = exp(dt)
//  (the exp(-dt[l]) base cancels -> 12 exps per 4 elements).
//  windowed numerators: num_c = sum_{m=c+1}^{c+8} E[m]*x[m] -> the 4 elements
//  of a float4 share the products p[m] = E[m]*x[m]: 11 MUL + 14 ADD replaces
//  32 FMA. at[l] = num*rcp(den);  at[l<7] = 0 exactly (BIG sentinel).
// ---------------------------------------------------------------------------
template<bool FIRST>
__device__ __forceinline__ void pass1_iter(
    const int j,
    const float4* __restrict__ dtr,
    const float4* __restrict__ xr0,
    const float4* __restrict__ xr1,
    const float*  __restrict__ ktr,     // [Kv] in registers
    float4* __restrict__ sat,           // [Gv*NJ]
    float4* __restrict__ sap,           // [Gv*NJ]
    float*  __restrict__ gr)            // [Gv*3] Gram accumulators
{
    const float4 zero4 = make_float4(0.f, 0.f, 0.f, 0.f);

    // dt window [4j-8 .. 4j+3] -> E = exp(dt)
    float4 dm2 = FIRST ? ((j >= 2) ? dtr[j - 2] : zero4) : dtr[j - 2];
    float4 dm1 = FIRST ? ((j >= 1) ? dtr[j - 1] : zero4) : dtr[j - 1];
    float4 dd0 = dtr[j];
    float Ew[12] = {dm2.x, dm2.y, dm2.z, dm2.w,
                    dm1.x, dm1.y, dm1.z, dm1.w,
                    dd0.x, dd0.y, dd0.z, dd0.w};
#pragma unroll
    for (int m = 0; m < 12; m++) Ew[m] = __expf(Ew[m]);

    // reciprocal 8-tap sums (shared factored partials)
    float inv[4];
    {
        float c45  = Ew[4] + Ew[5];
        float c67  = Ew[6] + Ew[7];
        float core = (c45 + c67) + Ew[8];          // E[4..8]
        float s23  = Ew[2] + Ew[3];
        float s910 = Ew[9] + Ew[10];
        inv[0] = __fdividef(1.0f, core + (Ew[1] + s23));    // E[1..8]
        inv[1] = __fdividef(1.0f, core + (s23 + Ew[9]));    // E[2..9]
        inv[2] = __fdividef(1.0f, core + (Ew[3] + s910));   // E[3..10]
        inv[3] = __fdividef(1.0f, core + (s910 + Ew[11]));  // E[4..11]
    }

#pragma unroll
    for (int g = 0; g < Gv; g++) {
        const float4* xr = (g == 0) ? xr0 : xr1;
        float4 xm2 = FIRST ? ((j >= 2) ? xr[j - 2] : zero4) : xr[j - 2];
        float4 xm1 = FIRST ? ((j >= 1) ? xr[j - 1] : zero4) : xr[j - 1];
        float4 x0  = xr[j];
        float xw[12] = {xm2.x, xm2.y, xm2.z, xm2.w,
                        xm1.x, xm1.y, xm1.z, xm1.w,
                        x0.x,  x0.y,  x0.z,  x0.w};

        // products p[m] = E[m]*x[m], m = 1..11; windowed numerators
        float num[4];
        {
            float p1 = Ew[1] * xw[1],  p2 = Ew[2] * xw[2],  p3 = Ew[3] * xw[3];
            float p4 = Ew[4] * xw[4],  p5 = Ew[5] * xw[5],  p6 = Ew[6] * xw[6];
            float p7 = Ew[7] * xw[7],  p8 = Ew[8] * xw[8],  p9 = Ew[9] * xw[9];
            float p10 = Ew[10] * xw[10], p11 = Ew[11] * xw[11];
            float c45  = p4 + p5;
            float c67  = p6 + p7;
            float core = (c45 + c67) + p8;         // p[4..8]
            float s23  = p2 + p3;
            float s910 = p9 + p10;
            num[0] = core + (p1 + s23);            // p[1..8]
            num[1] = core + (s23 + p9);            // p[2..9]
            num[2] = core + (p3 + s910);           // p[3..10]
            num[3] = core + (s910 + p11);          // p[4..11]
        }

        float4 atv, apv;
        float* atf = (float*)&atv;
        float* apf = (float*)&apv;
#pragma unroll
        for (int c = 0; c < 4; c++) {
            float a_p = 0.f;
#pragma unroll
            for (int k = 0; k < Kv; k++)
                a_p = fmaf(ktr[k], xw[8 + c - k], a_p);
            float a_t = num[c] * inv[c];
            if (FIRST) {
                if (4 * j + c < Kv - 1) a_t = 0.f;   // BIG-sentinel mask
            }
            atf[c] = a_t;
            apf[c] = a_p;
            gr[g * 3 + 0] = fmaf(a_t, a_t, gr[g * 3 + 0]);
            gr[g * 3 + 1] = fmaf(a_t, a_p, gr[g * 3 + 1]);
            gr[g * 3 + 2] = fmaf(a_p, a_p, gr[g * 3 + 2]);
        }
        sat[g * NJ + j] = atv;
        sap[g * NJ + j] = apv;
    }
}

__global__ void __launch_bounds__(TPB, 3) fused_kernel(
    const float* __restrict__ x,
    const float* __restrict__ dt,
    const float* __restrict__ kt,
    float* __restrict__ out)
{
    extern __shared__ float smem[];
    float4* sat = (float4*)smem;               // [Gv][NJ]
    float4* sap = (float4*)(smem + Gv * Lv);   // [Gv][NJ]
    __shared__ float sred[8][Gv * 3];
    __shared__ float scoef[Gv][2];

    const int b   = blockIdx.x >> 7;           // / (Cv/Gv = 128)
    const int c0  = (blockIdx.x & 127) * Gv;
    const int tid = threadIdx.x;
    const int lid = tid & 31;
    const int wid = tid >> 5;

    const float4* dtr = (const float4*)(dt + (size_t)b * Lv);
    const float4* xr0 = (const float4*)(x + (size_t)(b * Cv + c0 + 0) * Lv);
    const float4* xr1 = (const float4*)(x + (size_t)(b * Cv + c0 + 1) * Lv);

    float ktr[Kv];
#pragma unroll
    for (int k = 0; k < Kv; k++) ktr[k] = __ldg(&kt[k]);

    float gr[Gv * 3];
#pragma unroll
    for (int q = 0; q < Gv * 3; q++) gr[q] = 0.f;

    // Iteration 0 (peeled: halo zero-fill + l<7 mask live only here)
    pass1_iter<true>(tid, dtr, xr0, xr1, ktr, sat, sap, gr);
    // Iterations 1..3: FULLY UNROLLED so ptxas can batch the LDGs of later
    // iterations above earlier compute (MLP up, long-scoreboard exposure down).
#pragma unroll
    for (int i = 1; i < ITERS; i++)
        pass1_iter<false>(tid + i * TPB, dtr, xr0, xr1, ktr, sat, sap, gr);

    // ---- block reduction of 6 Gram scalars ----
#pragma unroll
    for (int q = 0; q < Gv * 3; q++) {
        float v = gr[q];
#pragma unroll
        for (int o = 16; o > 0; o >>= 1)
            v += __shfl_xor_sync(0xffffffffu, v, o);
        if (lid == 0) sred[wid][q] = v;
    }
    __syncthreads();
    if (tid < Gv) {
        float G00 = 0.f, G01 = 0.f, G11 = 0.f;
#pragma unroll
        for (int wq = 0; wq < 8; wq++) {
            G00 += sred[wq][tid * 3 + 0];
            G01 += sred[wq][tid * 3 + 1];
            G11 += sred[wq][tid * 3 + 2];
        }
        // scores row0 = softmax([G00,G01]); row1 = softmax([G01,G11])
        // out = 0.5*((s00+s10)*at + ((1-s00)+(1-s10))*ap)
        float s00 = 1.0f / (1.0f + __expf(G01 - G00));
        float s10 = 1.0f / (1.0f + __expf(G11 - G01));
        scoef[tid][0] = 0.5f * (s00 + s10);
        scoef[tid][1] = 0.5f * ((1.0f - s00) + (1.0f - s10));
    }
    __syncthreads();

    // ---- pass 2: out = ca*at + cb*ap (LDS.128 -> STG.128) ----
#pragma unroll
    for (int g = 0; g < Gv; g++) {
        const float ca = scoef[g][0];
        const float cb = scoef[g][1];
        float4* orow = (float4*)(out + (size_t)(b * Cv + c0 + g) * Lv);
#pragma unroll
        for (int i = 0; i < ITERS; i++) {
            const int j = tid + i * TPB;
            float4 a = sat[g * NJ + j];
            float4 p = sap[g * NJ + j];
            float4 o;
            o.x = fmaf(ca, a.x, cb * p.x);
            o.y = fmaf(ca, a.y, cb * p.y);
            o.z = fmaf(ca, a.z, cb * p.z);
            o.w = fmaf(ca, a.w, cb * p.w);
            orow[j] = o;
        }
    }
}

// ---------------------------------------------------------------------------
extern "C" void kernel_launch(void* const* d_in, const int* in_sizes, int n_in,
                              void* d_out, int out_size) {
    const float* x  = (const float*)d_in[0];   // (B, C, L) f32
    const float* dt = (const float*)d_in[1];   // (B, L)    f32
    const float* kt = (const float*)d_in[2];   // (1, 1, K) f32
    float* out = (float*)d_out;                // (B, C, L) f32

    cudaFuncSetAttribute(fused_kernel,
                         cudaFuncAttributeMaxDynamicSharedMemorySize, SMEM_BYTES);

    fused_kernel<<<Bv * Cv / Gv, TPB, SMEM_BYTES>>>(x, dt, kt, out);
}